// round 6
// baseline (speedup 1.0000x reference)
#include <cuda_runtime.h>

// MultiHeadAttentionQuantum — closed-form reduction (R1 derivation):
//   c_u = cos(q_u + phi_u);  out_w = prod_{u<=w} c_u (w>=1);  out_0 = prod_{u=1..7} c_u
//   y = Wc @ out + bc.  k/v are dead code in the reference.
//
// R5 = R4 resubmit (R4 bench was an infra failure, kernel never measured):
// 4 threads per token (2 wires each), 131072 threads -> ~27 warps/SM;
// weights amortized in shared; feature/cos exchange via width-4 shuffles.

#define E_DIM 8

__global__ __launch_bounds__(256)
void mhaq_kernel(const float* __restrict__ x,
                 const float* __restrict__ Wq, const float* __restrict__ bq,
                 const float* __restrict__ Wc, const float* __restrict__ bc,
                 const float* __restrict__ phi,
                 float* __restrict__ out)
{
    const unsigned FULL = 0xFFFFFFFFu;
    __shared__ float4 sWq[16], sWc[16];      // 8x8 each, row-major as float4
    __shared__ float  sBqp[8], sBc[8];       // bq+phi fused, bc

    int tid = threadIdx.x;
    int gtid = blockIdx.x * blockDim.x + tid;

    // Coalesced x load first (index == gtid for the float2 view) so DRAM
    // latency overlaps the weight staging + barrier.
    const float2* x2 = reinterpret_cast<const float2*>(x);
    float2 xv = x2[gtid];

    // Stage weights in shared.
    if (tid < 16) {
        sWq[tid] = reinterpret_cast<const float4*>(Wq)[tid];
        sWc[tid] = reinterpret_cast<const float4*>(Wc)[tid];
    }
    if (tid < 8) {
        sBqp[tid] = bq[tid] + phi[tid];
        sBc[tid]  = bc[tid];
    }
    __syncthreads();

    int p  = gtid & 3;        // pair index within token: wires 2p, 2p+1
    int r0 = 2 * p, r1 = 2 * p + 1;

    // Batch all LDS for this thread up front (broadcast, conflict-free).
    float4 qa0 = sWq[r0 * 2], qa1 = sWq[r0 * 2 + 1];
    float4 qb0 = sWq[r1 * 2], qb1 = sWq[r1 * 2 + 1];
    float4 ca0 = sWc[r0 * 2], ca1 = sWc[r0 * 2 + 1];
    float4 cb0 = sWc[r1 * 2], cb1 = sWc[r1 * 2 + 1];
    float q0 = sBqp[r0], q1 = sBqp[r1];
    float y0 = sBc[r0],  y1 = sBc[r1];

    // Gather all 8 features of this token (width-4 shuffle subgroups).
    float xr[8];
    #pragma unroll
    for (int e = 0; e < 4; e++) {
        xr[2 * e]     = __shfl_sync(FULL, xv.x, e, 4);
        xr[2 * e + 1] = __shfl_sync(FULL, xv.y, e, 4);
    }

    // q = Wq rows r0,r1 @ x + (bq+phi)
    q0 = fmaf(qa0.x, xr[0], q0); q1 = fmaf(qb0.x, xr[0], q1);
    q0 = fmaf(qa0.y, xr[1], q0); q1 = fmaf(qb0.y, xr[1], q1);
    q0 = fmaf(qa0.z, xr[2], q0); q1 = fmaf(qb0.z, xr[2], q1);
    q0 = fmaf(qa0.w, xr[3], q0); q1 = fmaf(qb0.w, xr[3], q1);
    q0 = fmaf(qa1.x, xr[4], q0); q1 = fmaf(qb1.x, xr[4], q1);
    q0 = fmaf(qa1.y, xr[5], q0); q1 = fmaf(qb1.y, xr[5], q1);
    q0 = fmaf(qa1.z, xr[6], q0); q1 = fmaf(qb1.z, xr[6], q1);
    q0 = fmaf(qa1.w, xr[7], q0); q1 = fmaf(qb1.w, xr[7], q1);

    float c0 = __cosf(q0), c1 = __cosf(q1);

    // Gather all 8 cosines.
    float c[8];
    #pragma unroll
    for (int e = 0; e < 4; e++) {
        c[2 * e]     = __shfl_sync(FULL, c0, e, 4);
        c[2 * e + 1] = __shfl_sync(FULL, c1, e, 4);
    }

    // Prefix products.
    float o[8];
    float pre = c[0];
    #pragma unroll
    for (int w = 1; w < 8; w++) { pre *= c[w]; o[w] = pre; }
    float suf = c[1];
    #pragma unroll
    for (int w = 2; w < 8; w++) suf *= c[w];
    o[0] = suf;

    // y for wires r0, r1.
    y0 = fmaf(ca0.x, o[0], y0); y1 = fmaf(cb0.x, o[0], y1);
    y0 = fmaf(ca0.y, o[1], y0); y1 = fmaf(cb0.y, o[1], y1);
    y0 = fmaf(ca0.z, o[2], y0); y1 = fmaf(cb0.z, o[2], y1);
    y0 = fmaf(ca0.w, o[3], y0); y1 = fmaf(cb0.w, o[3], y1);
    y0 = fmaf(ca1.x, o[4], y0); y1 = fmaf(cb1.x, o[4], y1);
    y0 = fmaf(ca1.y, o[5], y0); y1 = fmaf(cb1.y, o[5], y1);
    y0 = fmaf(ca1.z, o[6], y0); y1 = fmaf(cb1.z, o[6], y1);
    y0 = fmaf(ca1.w, o[7], y0); y1 = fmaf(cb1.w, o[7], y1);

    // Coalesced store: wires 2p,2p+1 of token t are float2 element gtid.
    reinterpret_cast<float2*>(out)[gtid] = make_float2(y0, y1);
}

extern "C" void kernel_launch(void* const* d_in, const int* in_sizes, int n_in,
                              void* d_out, int out_size)
{
    // metadata order: x, Wq, bq, Wk, bk, Wv, bv, Wc, bc, phi
    const float* x   = (const float*)d_in[0];
    const float* Wq  = (const float*)d_in[1];
    const float* bq  = (const float*)d_in[2];
    const float* Wc  = (const float*)d_in[7];
    const float* bc  = (const float*)d_in[8];
    const float* phi = (const float*)d_in[9];
    float* out = (float*)d_out;

    int n_tok = in_sizes[0] / E_DIM;          // 32768
    int total = n_tok * 4;                    // 131072 threads (2 wires each)
    int threads = 256;
    int blocks = total / threads;             // 512 (exact)
    mhaq_kernel<<<blocks, threads>>>(x, Wq, bq, Wc, bc, phi, out);
}

// round 7
// speedup vs baseline: 1.0337x; 1.0337x over previous
#include <cuda_runtime.h>

// MultiHeadAttentionQuantum — closed-form reduction (R1 derivation):
//   c_u = cos(q_u + phi_u);  out_w = prod_{u<=w} c_u (w>=1);  out_0 = prod_{u=1..7} c_u
//   y = Wc @ out + bc.  k/v are dead code in the reference.
//
// R7: back to the measured-best R2 body (1 token/thread — the split-token
// variants R3/R5 regressed on SHFL + instruction count). Only change:
// block 128 -> 64 (grid 512), continuing the measured small-block win
// (block256=5.76, block128=4.64). Weight staging split across both warps.

#define E_DIM 8

__global__ __launch_bounds__(64)
void mhaq_kernel(const float* __restrict__ x,
                 const float* __restrict__ Wq, const float* __restrict__ bq,
                 const float* __restrict__ Wc, const float* __restrict__ bc,
                 const float* __restrict__ phi,
                 float* __restrict__ out, int n_tok)
{
    __shared__ float4 sWq[16], sWc[16];
    __shared__ float  sBqp[8], sBc[8];

    int tid = threadIdx.x;
    int t = blockIdx.x * blockDim.x + tid;

    // x loads first: DRAM latency overlaps weight staging + barrier.
    const float4* xv = reinterpret_cast<const float4*>(x);
    float4 a = xv[2 * t];
    float4 b = xv[2 * t + 1];

    // Stage weights, spread across both warps of the 64-thread block.
    if (tid < 16) {
        sWq[tid] = reinterpret_cast<const float4*>(Wq)[tid];
    } else if (tid < 32) {
        sWc[tid - 16] = reinterpret_cast<const float4*>(Wc)[tid - 16];
    } else if (tid < 40) {
        int i = tid - 32;
        sBqp[i] = bq[i] + phi[i];
        sBc[i]  = bc[i];
    }
    __syncthreads();

    float xr[8] = {a.x, a.y, a.z, a.w, b.x, b.y, b.z, b.w};

    // q = Wq @ x + (bq + phi); c_u = cos(q_u) via MUFU.
    float c[8];
    #pragma unroll
    for (int u = 0; u < 8; u++) {
        float4 w0 = sWq[u * 2], w1 = sWq[u * 2 + 1];
        float qv = sBqp[u];
        qv = fmaf(w0.x, xr[0], qv); qv = fmaf(w0.y, xr[1], qv);
        qv = fmaf(w0.z, xr[2], qv); qv = fmaf(w0.w, xr[3], qv);
        qv = fmaf(w1.x, xr[4], qv); qv = fmaf(w1.y, xr[5], qv);
        qv = fmaf(w1.z, xr[6], qv); qv = fmaf(w1.w, xr[7], qv);
        c[u] = __cosf(qv);
    }

    // Prefix products.
    float o[8];
    float pre = c[0];
    #pragma unroll
    for (int w = 1; w < 8; w++) { pre *= c[w]; o[w] = pre; }
    float suf = c[1];
    #pragma unroll
    for (int w = 2; w < 8; w++) suf *= c[w];
    o[0] = suf;

    // y = Wc @ o + bc
    float y[8];
    #pragma unroll
    for (int u = 0; u < 8; u++) {
        float4 w0 = sWc[u * 2], w1 = sWc[u * 2 + 1];
        float v = sBc[u];
        v = fmaf(w0.x, o[0], v); v = fmaf(w0.y, o[1], v);
        v = fmaf(w0.z, o[2], v); v = fmaf(w0.w, o[3], v);
        v = fmaf(w1.x, o[4], v); v = fmaf(w1.y, o[5], v);
        v = fmaf(w1.z, o[6], v); v = fmaf(w1.w, o[7], v);
        y[u] = v;
    }

    float4* ov = reinterpret_cast<float4*>(out);
    ov[2 * t]     = make_float4(y[0], y[1], y[2], y[3]);
    ov[2 * t + 1] = make_float4(y[4], y[5], y[6], y[7]);
}

extern "C" void kernel_launch(void* const* d_in, const int* in_sizes, int n_in,
                              void* d_out, int out_size)
{
    // metadata order: x, Wq, bq, Wk, bk, Wv, bv, Wc, bc, phi
    const float* x   = (const float*)d_in[0];
    const float* Wq  = (const float*)d_in[1];
    const float* bq  = (const float*)d_in[2];
    const float* Wc  = (const float*)d_in[7];
    const float* bc  = (const float*)d_in[8];
    const float* phi = (const float*)d_in[9];
    float* out = (float*)d_out;

    int n_tok = in_sizes[0] / E_DIM;     // 32768
    int threads = 64;
    int blocks = n_tok / threads;        // 512 (exact)
    mhaq_kernel<<<blocks, threads>>>(x, Wq, bq, Wc, bc, phi, out, n_tok);
}

// round 8
// speedup vs baseline: 1.0750x; 1.0400x over previous
#include <cuda_runtime.h>

// MultiHeadAttentionQuantum — closed-form reduction (R1 derivation):
//   c_u = cos(q_u + phi_u);  out_w = prod_{u<=w} c_u (w>=1);  out_0 = prod_{u=1..7} c_u
//   y = Wc @ out + bc.  k/v are dead code in the reference.
//
// R8: 2 tokens per thread (split-halves: token gtid and gtid+16384 so all four
// LDG.128 stay fully coalesced), block=128, grid=128. Front-batched MLP=4 loads
// halve exposed DRAM latency; two independent compute streams per thread double
// ILP. Weights in smem (measured best), one barrier.

#define E_DIM 8

__global__ __launch_bounds__(128)
void mhaq_kernel(const float* __restrict__ x,
                 const float* __restrict__ Wq, const float* __restrict__ bq,
                 const float* __restrict__ Wc, const float* __restrict__ bc,
                 const float* __restrict__ phi,
                 float* __restrict__ out, int half_tok)
{
    __shared__ float4 sWq[16], sWc[16];
    __shared__ float  sBqp[8], sBc[8];

    int tid = threadIdx.x;
    int gtid = blockIdx.x * blockDim.x + tid;     // 0 .. half_tok-1
    int tA = gtid;
    int tB = gtid + half_tok;

    // Front-batch all four x loads (independent, MLP=4, coalesced 8 lines/req).
    const float4* xv = reinterpret_cast<const float4*>(x);
    float4 a0 = xv[2 * tA];
    float4 a1 = xv[2 * tA + 1];
    float4 b0 = xv[2 * tB];
    float4 b1 = xv[2 * tB + 1];

    // Stage weights in shared while the x loads are in flight.
    if (tid < 16) {
        sWq[tid] = reinterpret_cast<const float4*>(Wq)[tid];
        sWc[tid] = reinterpret_cast<const float4*>(Wc)[tid];
    }
    if (tid < 8) {
        sBqp[tid] = bq[tid] + phi[tid];
        sBc[tid]  = bc[tid];
    }
    __syncthreads();

    float xa[8] = {a0.x, a0.y, a0.z, a0.w, a1.x, a1.y, a1.z, a1.w};
    float xb[8] = {b0.x, b0.y, b0.z, b0.w, b1.x, b1.y, b1.z, b1.w};

    // q = Wq @ x + (bq+phi); c = cos(q). Two independent streams for ILP.
    float cA[8], cB[8];
    #pragma unroll
    for (int u = 0; u < 8; u++) {
        float4 w0 = sWq[u * 2], w1 = sWq[u * 2 + 1];
        float base = sBqp[u];
        float qa = base, qb = base;
        qa = fmaf(w0.x, xa[0], qa); qb = fmaf(w0.x, xb[0], qb);
        qa = fmaf(w0.y, xa[1], qa); qb = fmaf(w0.y, xb[1], qb);
        qa = fmaf(w0.z, xa[2], qa); qb = fmaf(w0.z, xb[2], qb);
        qa = fmaf(w0.w, xa[3], qa); qb = fmaf(w0.w, xb[3], qb);
        qa = fmaf(w1.x, xa[4], qa); qb = fmaf(w1.x, xb[4], qb);
        qa = fmaf(w1.y, xa[5], qa); qb = fmaf(w1.y, xb[5], qb);
        qa = fmaf(w1.z, xa[6], qa); qb = fmaf(w1.z, xb[6], qb);
        qa = fmaf(w1.w, xa[7], qa); qb = fmaf(w1.w, xb[7], qb);
        cA[u] = __cosf(qa);
        cB[u] = __cosf(qb);
    }

    // Prefix products for both tokens.
    float oA[8], oB[8];
    {
        float pa = cA[0], pb = cB[0];
        #pragma unroll
        for (int w = 1; w < 8; w++) {
            pa *= cA[w]; oA[w] = pa;
            pb *= cB[w]; oB[w] = pb;
        }
        float sa = cA[1], sb = cB[1];
        #pragma unroll
        for (int w = 2; w < 8; w++) { sa *= cA[w]; sb *= cB[w]; }
        oA[0] = sa; oB[0] = sb;
    }

    // y = Wc @ o + bc for both tokens.
    float yA[8], yB[8];
    #pragma unroll
    for (int u = 0; u < 8; u++) {
        float4 w0 = sWc[u * 2], w1 = sWc[u * 2 + 1];
        float base = sBc[u];
        float va = base, vb = base;
        va = fmaf(w0.x, oA[0], va); vb = fmaf(w0.x, oB[0], vb);
        va = fmaf(w0.y, oA[1], va); vb = fmaf(w0.y, oB[1], vb);
        va = fmaf(w0.z, oA[2], va); vb = fmaf(w0.z, oB[2], vb);
        va = fmaf(w0.w, oA[3], va); vb = fmaf(w0.w, oB[3], vb);
        va = fmaf(w1.x, oA[4], va); vb = fmaf(w1.x, oB[4], vb);
        va = fmaf(w1.y, oA[5], va); vb = fmaf(w1.y, oB[5], vb);
        va = fmaf(w1.z, oA[6], va); vb = fmaf(w1.z, oB[6], vb);
        va = fmaf(w1.w, oA[7], va); vb = fmaf(w1.w, oB[7], vb);
        yA[u] = va; yB[u] = vb;
    }

    float4* ov = reinterpret_cast<float4*>(out);
    ov[2 * tA]     = make_float4(yA[0], yA[1], yA[2], yA[3]);
    ov[2 * tA + 1] = make_float4(yA[4], yA[5], yA[6], yA[7]);
    ov[2 * tB]     = make_float4(yB[0], yB[1], yB[2], yB[3]);
    ov[2 * tB + 1] = make_float4(yB[4], yB[5], yB[6], yB[7]);
}

extern "C" void kernel_launch(void* const* d_in, const int* in_sizes, int n_in,
                              void* d_out, int out_size)
{
    // metadata order: x, Wq, bq, Wk, bk, Wv, bv, Wc, bc, phi
    const float* x   = (const float*)d_in[0];
    const float* Wq  = (const float*)d_in[1];
    const float* bq  = (const float*)d_in[2];
    const float* Wc  = (const float*)d_in[7];
    const float* bc  = (const float*)d_in[8];
    const float* phi = (const float*)d_in[9];
    float* out = (float*)d_out;

    int n_tok = in_sizes[0] / E_DIM;     // 32768
    int half  = n_tok / 2;               // 16384 threads
    int threads = 128;
    int blocks = half / threads;         // 128 (exact)
    mhaq_kernel<<<blocks, threads>>>(x, Wq, bq, Wc, bc, phi, out, half);
}